// round 4
// baseline (speedup 1.0000x reference)
#include <cuda_runtime.h>
#include <cuda_bf16.h>

// -------- constants from the reference --------
#define POOL_SIZE   32
#define PROMPT_LEN  32
#define NCTX        32
#define EMBED       768
#define TOP_K       5
#define N_CLS       1000
#define SUFFIX_LEN  12
#define EMBED_F4    (EMBED / 4)          // 192
#define CLS_F4      14784u               // 77*192
#define PROMPTS_F4  14784000u            // 1000*14784
#define SUF_F4      2304u                // 12*192

// Work decomposition: one unit = HALF a 192-f4 row (96 float4 = 1536 B).
//   Phase A (independent): 1000*45 prompt rows + 1056 pool/key rows
//                          = 46,056 rows = 92,112 units
//   Phase B (needs combined): 1000*32 rows = 64,000 units
#define NU_A        92112u
#define NU_B        64000u
#define GRID_X      888                  // 148 SMs * 6 blocks
#define BLOCK_X     256

// -------- device scratch / sync state (zero-init at load) --------
__device__ float4 g_combined4[PROMPT_LEN * EMBED_F4];
__device__ int      g_flag;
__device__ unsigned g_done;

// ============================================================
// Block 0's work: selection + gating + combined (256 threads)
// ============================================================
__device__ __forceinline__
void compute_combined(const float4* __restrict__ x4,
                      const float4* __restrict__ key4,
                      const float4* __restrict__ pool4,
                      const float4* __restrict__ aw4,
                      const float*  __restrict__ ab,
                      float4 (&qs4)[EMBED_F4],
                      float4 (&aw_s)[EMBED_F4],
                      float  (&sim)[POOL_SIZE],
                      int    (&idxs)[TOP_K])
{
    const int t = threadIdx.x;
    const int w = t >> 5, lane = t & 31;

    // ---- q = sum over 16 frames (mean scale & q-norm don't affect ordering)
    if (t < EMBED_F4) {
        float4 s = make_float4(0.f, 0.f, 0.f, 0.f);
        #pragma unroll
        for (int f = 0; f < 16; ++f) {
            float4 v = __ldg(&x4[f * EMBED_F4 + t]);
            s.x += v.x; s.y += v.y; s.z += v.z; s.w += v.w;
        }
        qs4[t] = s;
        aw_s[t] = __ldg(&aw4[t]);
    }
    __syncthreads();

    // ---- sims: 8 warps x 4 keys each; sim = (k.q)/||k|| (order-equiv cosine)
    #pragma unroll
    for (int j = 0; j < 4; ++j) {
        const int p = w + 8 * j;
        const float4* kp = key4 + p * EMBED_F4;
        float dot = 0.f, nrm = 0.f;
        #pragma unroll
        for (int i = 0; i < 6; ++i) {
            const int c = lane + i * 32;
            float4 kv = __ldg(&kp[c]), qv = qs4[c];
            dot += kv.x*qv.x + kv.y*qv.y + kv.z*qv.z + kv.w*qv.w;
            nrm += kv.x*kv.x + kv.y*kv.y + kv.z*kv.z + kv.w*kv.w;
        }
        #pragma unroll
        for (int o = 16; o; o >>= 1) {
            dot += __shfl_down_sync(0xffffffffu, dot, o);
            nrm += __shfl_down_sync(0xffffffffu, nrm, o);
        }
        if (lane == 0) sim[p] = dot * rsqrtf(nrm);
    }
    __syncthreads();

    // ---- top-5, strict '>' = lowest index wins ties (matches jax.lax.top_k)
    if (t == 0) {
        unsigned usedmask = 0u;
        for (int k = 0; k < TOP_K; ++k) {
            int best = 0; float bv = -3.0e38f;
            #pragma unroll
            for (int p = 0; p < POOL_SIZE; ++p)
                if (!((usedmask >> p) & 1u) && sim[p] > bv) { bv = sim[p]; best = p; }
            usedmask |= 1u << best;
            idxs[k] = best;
        }
    }
    __syncthreads();

    // ---- gating + weighted sum: 8 warps x 4 positions each
    const float ab0 = ab[0];
    #pragma unroll
    for (int j = 0; j < 4; ++j) {
        const int l = w + 8 * j;
        const float4* rows[TOP_K];
        #pragma unroll
        for (int k = 0; k < TOP_K; ++k)
            rows[k] = pool4 + (idxs[k] * PROMPT_LEN + l) * EMBED_F4;

        float dots[TOP_K] = {0.f, 0.f, 0.f, 0.f, 0.f};
        #pragma unroll
        for (int i = 0; i < 6; ++i) {
            const int c = lane + i * 32;
            float4 av = aw_s[c];
            #pragma unroll
            for (int k = 0; k < TOP_K; ++k) {
                float4 rv = __ldg(&rows[k][c]);
                dots[k] += rv.x*av.x + rv.y*av.y + rv.z*av.z + rv.w*av.w;
            }
        }
        #pragma unroll
        for (int k = 0; k < TOP_K; ++k) {
            #pragma unroll
            for (int o = 16; o; o >>= 1)
                dots[k] += __shfl_xor_sync(0xffffffffu, dots[k], o);
        }
        float wt[TOP_K];
        #pragma unroll
        for (int k = 0; k < TOP_K; ++k)
            wt[k] = 1.f / (1.f + __expf(-(dots[k] + ab0)));

        #pragma unroll
        for (int i = 0; i < 6; ++i) {
            const int c = lane + i * 32;
            float4 acc = make_float4(0.f, 0.f, 0.f, 0.f);
            #pragma unroll
            for (int k = 0; k < TOP_K; ++k) {
                float4 rv = __ldg(&rows[k][c]);      // L1 hit
                acc.x += wt[k]*rv.x; acc.y += wt[k]*rv.y;
                acc.z += wt[k]*rv.z; acc.w += wt[k]*rv.w;
            }
            g_combined4[l * EMBED_F4 + c] = acc;
        }
    }
}

// Half-row copy: 96 float4 per warp => 3 per lane (512B per instruction)
__device__ __forceinline__
void copy_half_stream(const float4* __restrict__ src, float4* __restrict__ dst, int lane)
{
    float4 v[3];
    #pragma unroll
    for (int i = 0; i < 3; ++i) v[i] = __ldcs(&src[lane + i * 32]);
    #pragma unroll
    for (int i = 0; i < 3; ++i) __stcs(&dst[lane + i * 32], v[i]);
}
__device__ __forceinline__
void copy_half_cached(const float4* __restrict__ src, float4* __restrict__ dst, int lane)
{
    float4 v[3];
    #pragma unroll
    for (int i = 0; i < 3; ++i) v[i] = __ldg(&src[lane + i * 32]);
    #pragma unroll
    for (int i = 0; i < 3; ++i) __stcs(&dst[lane + i * 32], v[i]);
}

// ============================================================
// The single persistent kernel
// ============================================================
__global__ __launch_bounds__(BLOCK_X, 6)
void k_all(const float4* __restrict__ x4,
           const float4* __restrict__ key4,
           const float4* __restrict__ pool4,
           const float4* __restrict__ aw4,
           const float*  __restrict__ ab,
           const float4* __restrict__ pre4,
           const float4* __restrict__ suf4,
           const float4* __restrict__ ctx4,
           float4* __restrict__ out)
{
    __shared__ float4 qs4[EMBED_F4];
    __shared__ float4 aw_s[EMBED_F4];
    __shared__ float  sim[POOL_SIZE];
    __shared__ int    idxs[TOP_K];

    const int t = threadIdx.x;
    const int w = t >> 5, lane = t & 31;
    const unsigned b = blockIdx.x;
    const unsigned nb = gridDim.x;

    if (b == 0) {
        compute_combined(x4, key4, pool4, aw4, ab, qs4, aw_s, sim, idxs);
        __syncthreads();
        __threadfence();
        if (t == 0) atomicExch(&g_flag, 1);
    } else {
        // ---- Phase A: everything independent of 'combined'
        const unsigned WA = (nb - 1u) * 8u;            // warps in phase A
        for (unsigned u = (b - 1u) * 8u + (unsigned)w; u < NU_A; u += WA) {
            const unsigned R = u >> 1;
            const unsigned hofs = (u & 1u) * 96u;
            if (R < 45000u) {
                const unsigned c = R / 45u;            // magic-multiply
                const unsigned r = R - c * 45u;
                if (r == 0u) {
                    copy_half_stream(pre4 + c * EMBED_F4 + hofs,
                                     out + c * CLS_F4 + hofs, lane);
                } else if (r <= 32u) {
                    // ctx row: re-read 1000x -> keep cached
                    copy_half_cached(ctx4 + (r - 1u) * EMBED_F4 + hofs,
                                     out + c * CLS_F4 + (r + 32u) * EMBED_F4 + hofs, lane);
                } else {
                    copy_half_stream(suf4 + c * SUF_F4 + (r - 33u) * EMBED_F4 + hofs,
                                     out + c * CLS_F4 + (r + 32u) * EMBED_F4 + hofs, lane);
                }
            } else {
                const unsigned q = R - 45000u;         // 0..1055: pool then key
                const float4* src = (q < 1024u) ? (pool4 + q * EMBED_F4)
                                                : (key4 + (q - 1024u) * EMBED_F4);
                copy_half_stream(src + hofs,
                                 out + PROMPTS_F4 + q * EMBED_F4 + hofs, lane);
            }
        }
        // ---- wait for combined
        if (t == 0) {
            while (atomicAdd(&g_flag, 0) == 0) __nanosleep(64);
        }
        __syncthreads();
        __threadfence();
    }

    // ---- Phase B: the 32 combined rows broadcast to 1000 classes
    {
        const unsigned WB = nb * 8u;
        const float4* __restrict__ cmb4 = g_combined4;
        for (unsigned u = b * 8u + (unsigned)w; u < NU_B; u += WB) {
            const unsigned R = u >> 1;
            const unsigned hofs = (u & 1u) * 96u;
            const unsigned c = R >> 5;
            const unsigned r = R & 31u;
            copy_half_cached(cmb4 + r * EMBED_F4 + hofs,
                             out + c * CLS_F4 + (r + 1u) * EMBED_F4 + hofs, lane);
        }
    }

    // ---- self-reset sync state so every graph replay starts clean
    __syncthreads();
    if (t == 0) {
        __threadfence();
        unsigned prev = atomicAdd(&g_done, 1u);
        if (prev == nb - 1u) { g_done = 0u; g_flag = 0; }
    }
}

// ============================================================
extern "C" void kernel_launch(void* const* d_in, const int* in_sizes, int n_in,
                              void* d_out, int out_size)
{
    const float* x_embed      = (const float*)d_in[0];
    const float* prompt_pool  = (const float*)d_in[1];
    const float* prompt_key   = (const float*)d_in[2];
    const float* alpha_w      = (const float*)d_in[3];
    const float* alpha_b      = (const float*)d_in[4];
    const float* ctx          = (const float*)d_in[5];
    const float* token_prefix = (const float*)d_in[6];
    const float* token_suffix = (const float*)d_in[7];
    // d_in[8] = train_flag: the penalty is a positive scalar on sims ->
    // top-k ordering (and therefore the output) is unchanged; safely ignored.

    k_all<<<GRID_X, BLOCK_X>>>((const float4*)x_embed,
                               (const float4*)prompt_key,
                               (const float4*)prompt_pool,
                               (const float4*)alpha_w,
                               alpha_b,
                               (const float4*)token_prefix,
                               (const float4*)token_suffix,
                               (const float4*)ctx,
                               (float4*)d_out);
}

// round 5
// speedup vs baseline: 1.2430x; 1.2430x over previous
#include <cuda_runtime.h>
#include <cuda_bf16.h>

// -------- constants from the reference --------
#define POOL_SIZE   32
#define PROMPT_LEN  32
#define NCTX        32
#define EMBED       768
#define TOP_K       5
#define N_CLS       1000
#define SUFFIX_LEN  12
#define EMBED_F4    (EMBED / 4)          // 192
#define CLS_F4      14784u               // 77*192
#define PROMPTS_F4  14784000u            // 1000*14784
#define SUF_F4      2304u                // 12*192

// Row-granular work (one row = 192 float4 = 3 KB, one warp-iter, MLP=6/lane)
//   Phase A (independent of selection): 1000*45 + 1056 pool/key = 46,056 rows
//   Phase B (needs combined):           1000*32               = 32,000 rows
#define NROWS_A     46056u
#define NROWS_B     32000u
#define GRID_X      148                  // exactly one wave, 1 block/SM
#define BLOCK_X     1024

#define CTX_F4      (NCTX * EMBED_F4)        // 6144 float4 = 96 KB
#define CMB_F4      (PROMPT_LEN * EMBED_F4)  // 6144 float4 = 96 KB
#define DYN_SMEM_BYTES ((CTX_F4 + CMB_F4) * 16)

// -------- device scratch / sync state (zero-init at load) --------
__device__ float4 g_combined4[CMB_F4];
__device__ int      g_flag;
__device__ unsigned g_done;

// Row copy helpers: 192 float4 per warp => 6 per lane (512B per instruction)
__device__ __forceinline__
void copy_row_stream(const float4* __restrict__ src, float4* __restrict__ dst, int lane)
{
    float4 v[6];
    #pragma unroll
    for (int i = 0; i < 6; ++i) v[i] = __ldcs(&src[lane + i * 32]);
    #pragma unroll
    for (int i = 0; i < 6; ++i) __stcs(&dst[lane + i * 32], v[i]);
}
__device__ __forceinline__
void copy_row_smem(const float4* __restrict__ src_s, float4* __restrict__ dst, int lane)
{
    float4 v[6];
    #pragma unroll
    for (int i = 0; i < 6; ++i) v[i] = src_s[lane + i * 32];   // LDS.128
    #pragma unroll
    for (int i = 0; i < 6; ++i) __stcs(&dst[lane + i * 32], v[i]);
}

// ============================================================
// Block 0's work: selection + gating + combined (1024 threads)
// Writes result to g_combined4 (for other blocks) AND cmb_s (own smem).
// ============================================================
__device__ __forceinline__
void compute_combined(const float4* __restrict__ x4,
                      const float4* __restrict__ key4,
                      const float4* __restrict__ pool4,
                      const float4* __restrict__ aw4,
                      const float*  __restrict__ ab,
                      float4* __restrict__ cmb_s,
                      float4 (&qs4)[EMBED_F4],
                      float4 (&aw_s)[EMBED_F4],
                      float  (&sim)[POOL_SIZE],
                      int    (&idxs)[TOP_K])
{
    const int t = threadIdx.x;
    const int w = t >> 5, lane = t & 31;

    // ---- q = sum over 16 frames (mean scale & q-norm don't affect top-k)
    if (t < EMBED_F4) {
        float4 s = make_float4(0.f, 0.f, 0.f, 0.f);
        #pragma unroll
        for (int f = 0; f < 16; ++f) {
            float4 v = __ldg(&x4[f * EMBED_F4 + t]);
            s.x += v.x; s.y += v.y; s.z += v.z; s.w += v.w;
        }
        qs4[t] = s;
        aw_s[t] = __ldg(&aw4[t]);
    }
    __syncthreads();

    // ---- one warp per pool key: sim = (k.q)/||k|| (cosine-order equivalent)
    {
        const float4* kp = key4 + w * EMBED_F4;
        float dot = 0.f, nrm = 0.f;
        #pragma unroll
        for (int i = 0; i < 6; ++i) {
            const int c = lane + i * 32;
            float4 kv = __ldg(&kp[c]), qv = qs4[c];
            dot += kv.x*qv.x + kv.y*qv.y + kv.z*qv.z + kv.w*qv.w;
            nrm += kv.x*kv.x + kv.y*kv.y + kv.z*kv.z + kv.w*kv.w;
        }
        #pragma unroll
        for (int o = 16; o; o >>= 1) {
            dot += __shfl_down_sync(0xffffffffu, dot, o);
            nrm += __shfl_down_sync(0xffffffffu, nrm, o);
        }
        if (lane == 0) sim[w] = dot * rsqrtf(nrm);
    }
    __syncthreads();

    // ---- top-5, strict '>' = lowest index wins ties (matches jax.lax.top_k)
    if (t == 0) {
        unsigned usedmask = 0u;
        for (int k = 0; k < TOP_K; ++k) {
            int best = 0; float bv = -3.0e38f;
            #pragma unroll
            for (int p = 0; p < POOL_SIZE; ++p)
                if (!((usedmask >> p) & 1u) && sim[p] > bv) { bv = sim[p]; best = p; }
            usedmask |= 1u << best;
            idxs[k] = best;
        }
    }
    __syncthreads();

    // ---- one warp per token position l = w: gates + weighted sum
    const float ab0 = ab[0];
    const float4* rows[TOP_K];
    #pragma unroll
    for (int k = 0; k < TOP_K; ++k)
        rows[k] = pool4 + (idxs[k] * PROMPT_LEN + w) * EMBED_F4;

    float dots[TOP_K] = {0.f, 0.f, 0.f, 0.f, 0.f};
    #pragma unroll
    for (int i = 0; i < 6; ++i) {
        const int c = lane + i * 32;
        float4 av = aw_s[c];
        #pragma unroll
        for (int k = 0; k < TOP_K; ++k) {
            float4 rv = __ldg(&rows[k][c]);
            dots[k] += rv.x*av.x + rv.y*av.y + rv.z*av.z + rv.w*av.w;
        }
    }
    #pragma unroll
    for (int k = 0; k < TOP_K; ++k) {
        #pragma unroll
        for (int o = 16; o; o >>= 1)
            dots[k] += __shfl_xor_sync(0xffffffffu, dots[k], o);
    }
    float wt[TOP_K];
    #pragma unroll
    for (int k = 0; k < TOP_K; ++k)
        wt[k] = 1.f / (1.f + __expf(-(dots[k] + ab0)));

    #pragma unroll
    for (int i = 0; i < 6; ++i) {
        const int c = lane + i * 32;
        float4 acc = make_float4(0.f, 0.f, 0.f, 0.f);
        #pragma unroll
        for (int k = 0; k < TOP_K; ++k) {
            float4 rv = __ldg(&rows[k][c]);      // L1 hit
            acc.x += wt[k]*rv.x; acc.y += wt[k]*rv.y;
            acc.z += wt[k]*rv.z; acc.w += wt[k]*rv.w;
        }
        g_combined4[w * EMBED_F4 + c] = acc;
        cmb_s[w * EMBED_F4 + c] = acc;           // own smem copy for phase B
    }
}

// ============================================================
// The single persistent kernel
// ============================================================
__global__ __launch_bounds__(BLOCK_X, 1)
void k_all(const float4* __restrict__ x4,
           const float4* __restrict__ key4,
           const float4* __restrict__ pool4,
           const float4* __restrict__ aw4,
           const float*  __restrict__ ab,
           const float4* __restrict__ pre4,
           const float4* __restrict__ suf4,
           const float4* __restrict__ ctx4,
           float4* __restrict__ out)
{
    extern __shared__ float4 dyn_s[];
    float4* __restrict__ ctx_s = dyn_s;            // [CTX_F4]
    float4* __restrict__ cmb_s = dyn_s + CTX_F4;   // [CMB_F4]

    __shared__ float4 qs4[EMBED_F4];
    __shared__ float4 aw_s[EMBED_F4];
    __shared__ float  sim[POOL_SIZE];
    __shared__ int    idxs[TOP_K];

    const int t = threadIdx.x;
    const int w = t >> 5, lane = t & 31;
    const unsigned b = blockIdx.x;
    const unsigned nb = gridDim.x;

    if (b == 0) {
        // ---- selection + gating + combined on a private SM, then release
        compute_combined(x4, key4, pool4, aw4, ab, cmb_s, qs4, aw_s, sim, idxs);
        __syncthreads();
        __threadfence();
        if (t == 0) atomicExch(&g_flag, 1);
        // block 0 skips phase A; goes straight to phase B below
    } else {
        // ---- stage ctx into SMEM: warp w loads row w (L2-hit for most blocks)
        {
            const float4* src = ctx4 + w * EMBED_F4;
            float4* dst = ctx_s + w * EMBED_F4;
            #pragma unroll
            for (int i = 0; i < 6; ++i) dst[lane + i * 32] = __ldg(&src[lane + i * 32]);
        }
        __syncthreads();

        // ---- Phase A: everything independent of 'combined'
        const unsigned WA = (nb - 1u) * 32u;
        for (unsigned R = (b - 1u) * 32u + (unsigned)w; R < NROWS_A; R += WA) {
            if (R < 45000u) {
                const unsigned c = R / 45u;            // magic-multiply
                const unsigned r = R - c * 45u;
                if (r == 0u) {
                    copy_row_stream(pre4 + c * EMBED_F4,
                                    out + c * CLS_F4, lane);
                } else if (r <= 32u) {
                    copy_row_smem(ctx_s + (r - 1u) * EMBED_F4,
                                  out + c * CLS_F4 + (r + 32u) * EMBED_F4, lane);
                } else {
                    copy_row_stream(suf4 + c * SUF_F4 + (r - 33u) * EMBED_F4,
                                    out + c * CLS_F4 + (r + 32u) * EMBED_F4, lane);
                }
            } else {
                const unsigned q = R - 45000u;         // 0..1055: pool then key
                const float4* src = (q < 1024u) ? (pool4 + q * EMBED_F4)
                                                : (key4 + (q - 1024u) * EMBED_F4);
                copy_row_stream(src, out + PROMPTS_F4 + q * EMBED_F4, lane);
            }
        }

        // ---- wait for combined, then stage it into SMEM
        if (t == 0) {
            while (atomicAdd(&g_flag, 0) == 0) __nanosleep(64);
        }
        __syncthreads();
        __threadfence();
        {
            const float4* src = g_combined4 + w * EMBED_F4;   // L2-hot
            float4* dst = cmb_s + w * EMBED_F4;
            #pragma unroll
            for (int i = 0; i < 6; ++i) dst[lane + i * 32] = __ldg(&src[lane + i * 32]);
        }
        __syncthreads();
    }

    // ---- Phase B: 32 combined rows broadcast to 1000 classes, src = SMEM
    {
        const unsigned WB = nb * 32u;
        for (unsigned R = b * 32u + (unsigned)w; R < NROWS_B; R += WB) {
            const unsigned c = R >> 5;
            const unsigned r = R & 31u;
            copy_row_smem(cmb_s + r * EMBED_F4,
                          out + c * CLS_F4 + (r + 1u) * EMBED_F4, lane);
        }
    }

    // ---- self-reset sync state so every graph replay starts clean
    __syncthreads();
    if (t == 0) {
        __threadfence();
        unsigned prev = atomicAdd(&g_done, 1u);
        if (prev == nb - 1u) { g_done = 0u; g_flag = 0; }
    }
}

// ============================================================
extern "C" void kernel_launch(void* const* d_in, const int* in_sizes, int n_in,
                              void* d_out, int out_size)
{
    const float* x_embed      = (const float*)d_in[0];
    const float* prompt_pool  = (const float*)d_in[1];
    const float* prompt_key   = (const float*)d_in[2];
    const float* alpha_w      = (const float*)d_in[3];
    const float* alpha_b      = (const float*)d_in[4];
    const float* ctx          = (const float*)d_in[5];
    const float* token_prefix = (const float*)d_in[6];
    const float* token_suffix = (const float*)d_in[7];
    // d_in[8] = train_flag: the penalty is a positive scalar on sims ->
    // top-k ordering (and therefore the output) is unchanged; safely ignored.

    static int attr_done = 0;
    if (!attr_done) {
        cudaFuncSetAttribute(k_all, cudaFuncAttributeMaxDynamicSharedMemorySize,
                             DYN_SMEM_BYTES);
        attr_done = 1;
    }

    k_all<<<GRID_X, BLOCK_X, DYN_SMEM_BYTES>>>(
        (const float4*)x_embed,
        (const float4*)prompt_key,
        (const float4*)prompt_pool,
        (const float4*)alpha_w,
        alpha_b,
        (const float4*)token_prefix,
        (const float4*)token_suffix,
        (const float4*)ctx,
        (float4*)d_out);
}